// round 13
// baseline (speedup 1.0000x reference)
#include <cuda_runtime.h>

#define NB 32
#define NCH 3
#define THREADS 128
#define B_PER_CHUNK 32
#define CHUNK_ELEMS (512*512)
#define CHUNK_F4   (CHUNK_ELEMS/4)         // 65536 float4 per (n,c) chunk
#define NCHUNKS    (16*3)                  // 48
#define NBLOCKS    (NCHUNKS * B_PER_CHUNK) // 1536 work blocks
#define STRIDE     (B_PER_CHUNK * THREADS) // 4096
#define NSLOTS 32                          // contention spreading for fp64 atomics

// Slot-spread accumulators: per-address atomic chain depth 1536/32 = 48 -> ~16
// per (slot,entry). Zero-initialized at module load; final_kernel resets after
// reading, so every (graph-replayed) launch starts clean.
__device__ double g_sum_d[NSLOTS][NCH * NB];
__device__ double g_cnt [NSLOTS][NCH * NB];

__device__ __forceinline__ void accum(float2* h, float xc, float pc, float tc, int tid)
{
    int b = (int)(xc * 32.0f);        // inputs uniform [0,1)
    b = min(b, NB - 1);               // x slightly <1 can round x*32 up to 32.0
    float2* e = &h[b * THREADS + tid];
    float2 v = *e;                    // LDS.64, conflict-free (lane stride 8B)
    v.x += pc - tc;
    v.y += 1.0f;
    *e = v;                           // STS.64
}

__global__ __launch_bounds__(THREADS, 7)
void hist_kernel(const float4* __restrict__ pred,
                 const float4* __restrict__ targ,
                 const float4* __restrict__ x)
{
    // Per-thread privatized {sum(p-t), count} histogram: h[bin*128 + tid].
    __shared__ float2 h[NB * THREADS];

    const int tid = threadIdx.x;

    #pragma unroll
    for (int b = 0; b < NB; b++)
        h[b * THREADS + tid] = make_float2(0.0f, 0.0f);
    __syncthreads();

    const int chunk = blockIdx.x / B_PER_CHUNK;   // (n*3 + c)
    const int sub   = blockIdx.x % B_PER_CHUNK;
    const int chan  = chunk % NCH;
    const int slot  = blockIdx.x & (NSLOTS - 1);
    const size_t base = (size_t)chunk * CHUNK_F4;

    int i = sub * THREADS + tid;
    #pragma unroll 2
    for (int k = 0; k < CHUNK_F4 / (2 * STRIDE); k++, i += 2 * STRIDE) {
        float4 xa = __ldcs(&x   [base + i]);
        float4 pa = __ldcs(&pred[base + i]);
        float4 ta = __ldcs(&targ[base + i]);
        float4 xb = __ldcs(&x   [base + i + STRIDE]);
        float4 pb = __ldcs(&pred[base + i + STRIDE]);
        float4 tb = __ldcs(&targ[base + i + STRIDE]);

        accum(h, xa.x, pa.x, ta.x, tid);
        accum(h, xa.y, pa.y, ta.y, tid);
        accum(h, xa.z, pa.z, ta.z, tid);
        accum(h, xa.w, pa.w, ta.w, tid);

        accum(h, xb.x, pb.x, tb.x, tid);
        accum(h, xb.y, pb.y, tb.y, tid);
        accum(h, xb.z, pb.z, tb.z, tid);
        accum(h, xb.w, pb.w, tb.w, tid);
    }
    __syncthreads();

    // Block reduce: 128 threads = 32 bins x 4 quarters of 32 entries.
    const int bin = tid >> 2;
    const int j   = tid & 3;
    const int bi  = bin * THREADS + j * 32;

    float vd = 0.0f, vc = 0.0f;
    #pragma unroll
    for (int k = 0; k < 32; k++) {
        int kk = (k + tid) & 31;
        float2 e = h[bi + kk];
        vd += e.x;
        vc += e.y;
    }

    vd += __shfl_down_sync(0xffffffffu, vd, 1);
    vc += __shfl_down_sync(0xffffffffu, vc, 1);
    vd += __shfl_down_sync(0xffffffffu, vd, 2);
    vc += __shfl_down_sync(0xffffffffu, vc, 2);

    if (j == 0) {
        int g = chan * NB + bin;
        // slot-spread -> short per-address chains -> fast end-of-kernel drain,
        // blocks retire promptly (fire-and-forget REDG, no return needed)
        atomicAdd(&g_sum_d[slot][g], (double)vd);
        atomicAdd(&g_cnt [slot][g], (double)vc);
    }
}

__global__ void final_kernel(float* __restrict__ out) {
    // PDL: launched early; blocks here until hist_kernel fully completes,
    // overlapping this kernel's launch/setup latency with hist execution.
    cudaGridDependencySynchronize();

    int i = threadIdx.x;
    float d = 0.0f;
    if (i < NCH * NB) {
        double sdv = 0.0, cnt = 0.0;
        #pragma unroll
        for (int s = 0; s < NSLOTS; s++) {
            sdv += g_sum_d[s][i];
            cnt += g_cnt [s][i];
            g_sum_d[s][i] = 0.0;   // reset for next launch (graph determinism)
            g_cnt [s][i] = 0.0;
        }
        if (cnt > 0.0) d = (float)fabs(sdv / cnt);
    }
    #pragma unroll
    for (int s = 16; s > 0; s >>= 1)
        d += __shfl_down_sync(0xffffffffu, d, s);

    __shared__ float wsum[4];
    if ((i & 31) == 0) wsum[i >> 5] = d;
    __syncthreads();
    if (i == 0) out[0] = (wsum[0] + wsum[1] + wsum[2] + wsum[3]) / 96.0f;
}

extern "C" void kernel_launch(void* const* d_in, const int* in_sizes, int n_in,
                              void* d_out, int out_size)
{
    const float4* pred = (const float4*)d_in[0];
    const float4* targ = (const float4*)d_in[1];
    const float4* x    = (const float4*)d_in[2];
    float* out = (float*)d_out;

    hist_kernel<<<NBLOCKS, THREADS>>>(pred, targ, x);

    cudaLaunchConfig_t cfg = {};
    cfg.gridDim  = dim3(1, 1, 1);
    cfg.blockDim = dim3(128, 1, 1);
    cfg.dynamicSmemBytes = 0;
    cfg.stream = 0;
    cudaLaunchAttribute attr[1];
    attr[0].id = cudaLaunchAttributeProgrammaticStreamSerialization;
    attr[0].val.programmaticStreamSerializationAllowed = 1;
    cfg.attrs = attr;
    cfg.numAttrs = 1;
    cudaLaunchKernelEx(&cfg, final_kernel, out);
}